// round 15
// baseline (speedup 1.0000x reference)
#include <cuda_runtime.h>
#include <cuda_bf16.h>

#define DCOLS 1024
#define NROWS 65536

__device__ __forceinline__ float sqrt_approx(float a) {
    float r; asm("sqrt.approx.f32 %0, %1;" : "=f"(r) : "f"(a)); return r;
}
__device__ __forceinline__ float rsqrt_approx(float a) {
    float r; asm("rsqrt.approx.f32 %0, %1;" : "=f"(r) : "f"(a)); return r;
}

// acos(x) = sqrt(1-x) * P(x) on [0,1], reflected for x<0.
// Abramowitz & Stegun 4.4.46-style 8-coefficient fit, |abs err| ~2e-8.
// The sqrt(1-x) prefactor keeps relative accuracy as x -> 1 (acos -> 0).
__device__ __forceinline__ float acos_fast(float x) {
    float t = fabsf(x);
    float p = fmaf(t, -0.0012624911f, 0.0066700901f);
    p = fmaf(p, t, -0.0170881256f);
    p = fmaf(p, t,  0.0308918810f);
    p = fmaf(p, t, -0.0501743046f);
    p = fmaf(p, t,  0.0889789874f);
    p = fmaf(p, t, -0.2145988016f);
    p = fmaf(p, t,  1.5707963050f);
    float r = sqrt_approx(1.0f - t) * p;
    return (x >= 0.0f) ? r : (3.14159265358979f - r);
}

// One warp per row. Lane L owns 32 contiguous elements [32L, 32L+32).
// Pass 1: 8x LDG.128 into registers, lane-local sum of squares.
// Warp suffix scan (5 shfl) gives each lane the sum of squares of all
// HIGHER lanes. Pass 2 walks the lane's elements from the tail,
// accumulating the running suffix sum s_j, and emits
//   out[j+1] = acos(x_j * rsqrt(s_j))          for j in [0, D-2]
// with the j == D-2 angle wrapped to 2*pi - phi when x_{D-1} < 0
// (lane 31 owns both, so no cross-lane traffic). Lane 0 finishes with
// the full sum and writes r = sqrt(s_0) at column 0.
__global__ void __launch_bounds__(256)
tohypersphere_kernel(const float* __restrict__ x, float* __restrict__ out) {
    const int warp = (blockIdx.x * blockDim.x + threadIdx.x) >> 5;
    const int lane = threadIdx.x & 31;
    if (warp >= NROWS) return;

    const float4* src =
        reinterpret_cast<const float4*>(x + (size_t)warp * DCOLS) + lane * 8;

    float v[32];
#pragma unroll
    for (int k = 0; k < 8; ++k) {
        float4 f = src[k];
        v[4 * k + 0] = f.x;
        v[4 * k + 1] = f.y;
        v[4 * k + 2] = f.z;
        v[4 * k + 3] = f.w;
    }

    // Lane-local total of squares.
    float T = 0.0f;
#pragma unroll
    for (int i = 0; i < 32; ++i) T = fmaf(v[i], v[i], T);

    // Inclusive suffix scan across lanes: sinc_L = sum_{L' >= L} T_{L'}.
    float sinc = T;
#pragma unroll
    for (int off = 1; off < 32; off <<= 1) {
        float o = __shfl_down_sync(0xffffffffu, sinc, off);
        if (lane + off < 32) sinc += o;
    }
    // Exclusive suffix = inclusive value of lane+1 (0 for lane 31).
    float S = __shfl_down_sync(0xffffffffu, sinc, 1);
    if (lane == 31) S = 0.0f;

    float* orow = out + (size_t)warp * DCOLS;
    const float TWO_PI = 6.283185307179586f;

    float s = S;
#pragma unroll
    for (int i = 31; i >= 0; --i) {
        s = fmaf(v[i], v[i], s);          // s = suffix sum at element j
        int j = lane * 32 + i;
        if (j < DCOLS - 1) {
            float z = v[i] * rsqrt_approx(s);
            // rsqrt.approx can overshoot |z| past 1 by a few ulp -> clamp
            z = fminf(1.0f, fmaxf(-1.0f, z));
            float phi = acos_fast(z);
            if (j == DCOLS - 2) {         // only lane 31, i == 30
                if (v[31] < 0.0f) phi = TWO_PI - phi;
            }
            orow[j + 1] = phi;
        }
    }

    if (lane == 0) orow[0] = sqrtf(s);    // s == full row sum of squares here
}

extern "C" void kernel_launch(void* const* d_in, const int* in_sizes, int n_in,
                              void* d_out, int out_size) {
    const float* x = (const float*)d_in[0];
    float* out = (float*)d_out;

    const int warps_per_block = 8;                  // 256 threads
    const int blocks = NROWS / warps_per_block;     // 8192 blocks
    tohypersphere_kernel<<<blocks, warps_per_block * 32>>>(x, out);
}

// round 16
// speedup vs baseline: 1.0064x; 1.0064x over previous
#include <cuda_runtime.h>
#include <cuda_bf16.h>

#define DCOLS 1024
#define NROWS 65536

__device__ __forceinline__ float sqrt_approx(float a) {
    float r; asm("sqrt.approx.f32 %0, %1;" : "=f"(r) : "f"(a)); return r;
}
__device__ __forceinline__ float rsqrt_approx(float a) {
    float r; asm("rsqrt.approx.f32 %0, %1;" : "=f"(r) : "f"(a)); return r;
}

// acos(x) = sqrt(1-x) * P(x) on [0,1], reflected for x<0.
// Abramowitz & Stegun 4.4.46-style 8-coefficient fit, |abs err| ~2e-8.
// The sqrt(1-x) prefactor keeps relative accuracy as x -> 1 (acos -> 0).
__device__ __forceinline__ float acos_fast(float x) {
    float t = fabsf(x);
    float p = fmaf(t, -0.0012624911f, 0.0066700901f);
    p = fmaf(p, t, -0.0170881256f);
    p = fmaf(p, t,  0.0308918810f);
    p = fmaf(p, t, -0.0501743046f);
    p = fmaf(p, t,  0.0889789874f);
    p = fmaf(p, t, -0.2145988016f);
    p = fmaf(p, t,  1.5707963050f);
    float r = sqrt_approx(1.0f - t) * p;
    return (x >= 0.0f) ? r : (3.14159265358979f - r);
}

// One warp per row. Lane L owns 32 contiguous elements [32L, 32L+32).
// Pass 1: 8x LDG.128 into registers, lane-local sum of squares.
// Warp suffix scan (5 shfl) gives each lane the sum of squares of all
// HIGHER lanes. Pass 2 walks the lane's elements from the tail,
// accumulating the running suffix sum s_j, and emits
//   out[j+1] = acos(x_j * rsqrt(s_j))          for j in [0, D-2]
// with the j == D-2 angle wrapped to 2*pi - phi when x_{D-1} < 0
// (lane 31 owns both, so no cross-lane traffic). Lane 0 finishes with
// the full sum and writes r = sqrt(s_0) at column 0.
__global__ void __launch_bounds__(256)
tohypersphere_kernel(const float* __restrict__ x, float* __restrict__ out) {
    const int warp = (blockIdx.x * blockDim.x + threadIdx.x) >> 5;
    const int lane = threadIdx.x & 31;
    if (warp >= NROWS) return;

    const float4* src =
        reinterpret_cast<const float4*>(x + (size_t)warp * DCOLS) + lane * 8;

    float v[32];
#pragma unroll
    for (int k = 0; k < 8; ++k) {
        float4 f = src[k];
        v[4 * k + 0] = f.x;
        v[4 * k + 1] = f.y;
        v[4 * k + 2] = f.z;
        v[4 * k + 3] = f.w;
    }

    // Lane-local total of squares.
    float T = 0.0f;
#pragma unroll
    for (int i = 0; i < 32; ++i) T = fmaf(v[i], v[i], T);

    // Inclusive suffix scan across lanes: sinc_L = sum_{L' >= L} T_{L'}.
    float sinc = T;
#pragma unroll
    for (int off = 1; off < 32; off <<= 1) {
        float o = __shfl_down_sync(0xffffffffu, sinc, off);
        if (lane + off < 32) sinc += o;
    }
    // Exclusive suffix = inclusive value of lane+1 (0 for lane 31).
    float S = __shfl_down_sync(0xffffffffu, sinc, 1);
    if (lane == 31) S = 0.0f;

    float* orow = out + (size_t)warp * DCOLS;
    const float TWO_PI = 6.283185307179586f;

    float s = S;
#pragma unroll
    for (int i = 31; i >= 0; --i) {
        s = fmaf(v[i], v[i], s);          // s = suffix sum at element j
        int j = lane * 32 + i;
        if (j < DCOLS - 1) {
            float z = v[i] * rsqrt_approx(s);
            // rsqrt.approx can overshoot |z| past 1 by a few ulp -> clamp
            z = fminf(1.0f, fmaxf(-1.0f, z));
            float phi = acos_fast(z);
            if (j == DCOLS - 2) {         // only lane 31, i == 30
                if (v[31] < 0.0f) phi = TWO_PI - phi;
            }
            orow[j + 1] = phi;
        }
    }

    if (lane == 0) orow[0] = sqrtf(s);    // s == full row sum of squares here
}

extern "C" void kernel_launch(void* const* d_in, const int* in_sizes, int n_in,
                              void* d_out, int out_size) {
    const float* x = (const float*)d_in[0];
    float* out = (float*)d_out;

    const int warps_per_block = 8;                  // 256 threads
    const int blocks = NROWS / warps_per_block;     // 8192 blocks
    tohypersphere_kernel<<<blocks, warps_per_block * 32>>>(x, out);
}